// round 2
// baseline (speedup 1.0000x reference)
#include <cuda_runtime.h>
#include <math.h>

#define TOKENS 2048
#define DM 1024
#define NH 16
#define HD 64

// ---------------- scratch (device globals: no allocs allowed) ----------------
__device__ float g_qraw[TOKENS * DM];
__device__ float g_kraw[TOKENS * DM];
__device__ float g_vraw[TOKENS * DM];
__device__ float g_beta[TOKENS * NH];
__device__ float g_att [TOKENS * DM];

// ---------------- generic NT GEMM: C[M,N] = A[M,K] * B[N,K]^T ----------------
// sel: 0 = use passed A/C; 1/2/3 = C -> g_qraw/g_kraw/g_vraw; 4 = A -> g_att
__global__ __launch_bounds__(256, 2)
void gemm_nt(const float* __restrict__ A_in, const float* __restrict__ B,
             float* __restrict__ C_in, int sel, int M, int N, int K)
{
    const float* A = A_in;
    float* C = C_in;
    if (sel == 1) C = g_qraw;
    else if (sel == 2) C = g_kraw;
    else if (sel == 3) C = g_vraw;
    else if (sel == 4) A = g_att;

    __shared__ float As[16][128];
    __shared__ float Bs[16][128];

    const int tid = threadIdx.x;
    const int m0 = blockIdx.y * 128;
    const int n0 = blockIdx.x * 128;
    const int tx = tid & 15, ty = tid >> 4;

    float acc[8][8];
#pragma unroll
    for (int i = 0; i < 8; i++)
#pragma unroll
        for (int j = 0; j < 8; j++) acc[i][j] = 0.f;

    for (int k0 = 0; k0 < K; k0 += 16) {
#pragma unroll
        for (int l = 0; l < 2; l++) {
            int fi = tid + l * 256;
            int row = fi >> 2;
            int kc = (fi & 3) << 2;
            float4 a = *(const float4*)(A + (size_t)(m0 + row) * K + k0 + kc);
            As[kc + 0][row] = a.x; As[kc + 1][row] = a.y;
            As[kc + 2][row] = a.z; As[kc + 3][row] = a.w;
            float4 b = *(const float4*)(B + (size_t)(n0 + row) * K + k0 + kc);
            Bs[kc + 0][row] = b.x; Bs[kc + 1][row] = b.y;
            Bs[kc + 2][row] = b.z; Bs[kc + 3][row] = b.w;
        }
        __syncthreads();
#pragma unroll
        for (int kk = 0; kk < 16; kk++) {
            float ar[8], br[8];
            *(float4*)&ar[0] = *(const float4*)&As[kk][ty * 4];
            *(float4*)&ar[4] = *(const float4*)&As[kk][64 + ty * 4];
            *(float4*)&br[0] = *(const float4*)&Bs[kk][tx * 4];
            *(float4*)&br[4] = *(const float4*)&Bs[kk][64 + tx * 4];
#pragma unroll
            for (int i = 0; i < 8; i++)
#pragma unroll
                for (int j = 0; j < 8; j++) acc[i][j] += ar[i] * br[j];
        }
        __syncthreads();
    }
#pragma unroll
    for (int i = 0; i < 8; i++) {
        int mr = m0 + (i < 4 ? ty * 4 + i : 64 + ty * 4 + (i - 4));
        float4 v0 = make_float4(acc[i][0], acc[i][1], acc[i][2], acc[i][3]);
        float4 v1 = make_float4(acc[i][4], acc[i][5], acc[i][6], acc[i][7]);
        *(float4*)(C + (size_t)mr * N + n0 + tx * 4) = v0;
        *(float4*)(C + (size_t)mr * N + n0 + 64 + tx * 4) = v1;
    }
}

// ---------------- beta = 2*sigmoid(x @ Wb^T), one warp per head ----------------
__global__ __launch_bounds__(512)
void beta_kernel(const float* __restrict__ x, const float* __restrict__ Wb)
{
    int token = blockIdx.x;
    int w = threadIdx.x >> 5;      // head 0..15
    int lane = threadIdx.x & 31;
    const float* xr = x + (size_t)token * DM;
    const float* wr = Wb + (size_t)w * DM;
    float s = 0.f;
    for (int j = lane; j < DM; j += 32) s += xr[j] * wr[j];
#pragma unroll
    for (int o = 16; o; o >>= 1) s += __shfl_xor_sync(0xffffffffu, s, o);
    if (lane == 0) g_beta[token * NH + w] = 2.f / (1.f + __expf(-s));
}

__device__ __forceinline__ float silu(float v) { return v / (1.f + __expf(-v)); }

// ------- silu + per-head L2 normalize for q,k; silu for v (in place) -------
__global__ __launch_bounds__(256)
void act_kernel()
{
    int token = blockIdx.x;
    int tid = threadIdx.x;                 // 16 threads per head (64 dims / 4)
    size_t off = (size_t)token * DM + tid * 4;

    // q
    float4 q = *(float4*)(g_qraw + off);
    q.x = silu(q.x); q.y = silu(q.y); q.z = silu(q.z); q.w = silu(q.w);
    float ss = q.x * q.x + q.y * q.y + q.z * q.z + q.w * q.w;
#pragma unroll
    for (int o = 8; o; o >>= 1) ss += __shfl_xor_sync(0xffffffffu, ss, o);
    float inv = 1.f / (sqrtf(ss) + 1e-6f);
    q.x *= inv; q.y *= inv; q.z *= inv; q.w *= inv;
    *(float4*)(g_qraw + off) = q;

    // k
    float4 k = *(float4*)(g_kraw + off);
    k.x = silu(k.x); k.y = silu(k.y); k.z = silu(k.z); k.w = silu(k.w);
    float sk = k.x * k.x + k.y * k.y + k.z * k.z + k.w * k.w;
#pragma unroll
    for (int o = 8; o; o >>= 1) sk += __shfl_xor_sync(0xffffffffu, sk, o);
    float invk = 1.f / (sqrtf(sk) + 1e-6f);
    k.x *= invk; k.y *= invk; k.z *= invk; k.w *= invk;
    *(float4*)(g_kraw + off) = k;

    // v
    float4 v = *(float4*)(g_vraw + off);
    v.x = silu(v.x); v.y = silu(v.y); v.z = silu(v.z); v.w = silu(v.w);
    *(float4*)(g_vraw + off) = v;
}

// ---------------- sequential delta-rule scan ----------------
// One CTA per (b,h). 256 threads. Dual state:
//   mcol[i] = M[qr*16+i][c]  (c = tid&63, qr = tid>>6)  -> for out = M^T q and col update
//   mrow[i] = M[r][qr*16+i]  (r = tid&63)               -> for retrieved = M k and row update
// Per step (reference order, read-before-update):
//   out[d]  = sum_h q[h] M[h][d]
//   r[h]    = sum_d M[h][d] k[d];  delta = v - r
//   M[h][d] += beta * k[h] * delta[d]
__global__ __launch_bounds__(256, 1)
void scan_kernel()
{
    const int pair = blockIdx.x;           // 0..31
    const int b = pair >> 4, h = pair & 15;
    const int tid = threadIdx.x;
    const int lane64 = tid & 63;
    const int qr = tid >> 6;
    const int base = qr * 16;

    __shared__ float q_sh[64], k_sh[64], v_sh[64], bd_sh[64];
    __shared__ float partR[4][64], partO[4][64];
    __shared__ float beta_sh;

    float mcol[16], mrow[16];
#pragma unroll
    for (int i = 0; i < 16; i++) { mcol[i] = 0.f; mrow[i] = 0.f; }

    const size_t hb = (size_t)b * 1024 * DM + h * HD;
    const float* qp = g_qraw + hb;
    const float* kp = g_kraw + hb;
    const float* vp = g_vraw + hb;
    const float* bp = g_beta + (size_t)b * 1024 * NH + h;
    float* op = g_att + hb;

    for (int t = 0; t < 1024; t++) {
        if (tid < 64)        q_sh[tid]        = qp[(size_t)t * DM + tid];
        else if (tid < 128)  k_sh[tid - 64]   = kp[(size_t)t * DM + tid - 64];
        else if (tid < 192)  v_sh[tid - 128]  = vp[(size_t)t * DM + tid - 128];
        else if (tid == 192) beta_sh          = bp[(size_t)t * NH];
        __syncthreads();

        float pr = 0.f, po = 0.f;
#pragma unroll
        for (int i = 0; i < 16; i++) {
            pr += mrow[i] * k_sh[base + i];
            po += q_sh[base + i] * mcol[i];
        }
        partR[qr][lane64] = pr;
        partO[qr][lane64] = po;
        __syncthreads();

        if (tid < 64) {
            float rs = partR[0][tid] + partR[1][tid] + partR[2][tid] + partR[3][tid];
            bd_sh[tid] = beta_sh * (v_sh[tid] - rs);
        } else if (tid < 128) {
            int c = tid - 64;
            float os = partO[0][c] + partO[1][c] + partO[2][c] + partO[3][c];
            op[(size_t)t * DM + c] = os;
        }
        __syncthreads();

        const float bdc = bd_sh[lane64];   // delta*beta at column c
        const float kr  = k_sh[lane64];    // k at row r
#pragma unroll
        for (int i = 0; i < 16; i++) {
            mcol[i] += k_sh[base + i] * bdc;
            mrow[i] += kr * bd_sh[base + i];
        }
        __syncthreads();                   // protect smem before next load
    }
}

// ---------------- RMSNorm (in place on g_att) ----------------
__global__ __launch_bounds__(256)
void rms_kernel(const float* __restrict__ w)
{
    int token = blockIdx.x;
    int tid = threadIdx.x;
    size_t off = (size_t)token * DM + tid * 4;
    float4 v = *(float4*)(g_att + off);
    float ss = v.x * v.x + v.y * v.y + v.z * v.z + v.w * v.w;
#pragma unroll
    for (int o = 16; o; o >>= 1) ss += __shfl_xor_sync(0xffffffffu, ss, o);
    __shared__ float sh[8];
    __shared__ float sscale;
    if ((tid & 31) == 0) sh[tid >> 5] = ss;
    __syncthreads();
    if (tid == 0) {
        float t = 0.f;
#pragma unroll
        for (int i = 0; i < 8; i++) t += sh[i];
        sscale = 1.f / sqrtf(t / (float)DM + 1e-6f);
    }
    __syncthreads();
    float s = sscale;
    v.x *= s * w[tid * 4 + 0];
    v.y *= s * w[tid * 4 + 1];
    v.z *= s * w[tid * 4 + 2];
    v.w *= s * w[tid * 4 + 3];
    *(float4*)(g_att + off) = v;
}

// ---------------- launch ----------------
extern "C" void kernel_launch(void* const* d_in, const int* in_sizes, int n_in,
                              void* d_out, int out_size)
{
    const float* x    = (const float*)d_in[0];
    const float* Wq   = (const float*)d_in[1];
    const float* Wk   = (const float*)d_in[2];
    const float* Wv   = (const float*)d_in[3];
    const float* Wb   = (const float*)d_in[4];
    const float* Wo   = (const float*)d_in[5];
    const float* rmsw = (const float*)d_in[6];
    float* out = (float*)d_out;

    dim3 gg(DM / 128, TOKENS / 128);   // (8, 16)

    gemm_nt<<<gg, 256>>>(x, Wq, nullptr, 1, TOKENS, DM, DM);
    gemm_nt<<<gg, 256>>>(x, Wk, nullptr, 2, TOKENS, DM, DM);
    gemm_nt<<<gg, 256>>>(x, Wv, nullptr, 3, TOKENS, DM, DM);
    beta_kernel<<<TOKENS, 512>>>(x, Wb);
    act_kernel<<<TOKENS, 256>>>();
    scan_kernel<<<32, 256>>>();
    rms_kernel<<<TOKENS, 256>>>(rmsw);
    gemm_nt<<<gg, 256>>>(nullptr, Wo, out, 4, TOKENS, DM, DM);
}

// round 4
// speedup vs baseline: 1.4539x; 1.4539x over previous
#include <cuda_runtime.h>
#include <cuda_bf16.h>
#include <math.h>
#include <stdint.h>

#define TOKENS 2048
#define DM 1024
#define NH 16
#define HD 64

// ---------------- scratch (device globals: no allocs allowed) ----------------
__device__ float g_qraw[TOKENS * DM];
__device__ float g_kraw[TOKENS * DM];
__device__ float g_vraw[TOKENS * DM];
__device__ float g_beta[TOKENS * NH];
__device__ float g_att [TOKENS * DM];

__device__ __nv_bfloat16 g_xhi[TOKENS * DM], g_xlo[TOKENS * DM];
__device__ __nv_bfloat16 g_atthi[TOKENS * DM], g_attlo[TOKENS * DM];
__device__ __nv_bfloat16 g_wqhi[DM * DM], g_wqlo[DM * DM];
__device__ __nv_bfloat16 g_wkhi[DM * DM], g_wklo[DM * DM];
__device__ __nv_bfloat16 g_wvhi[DM * DM], g_wvlo[DM * DM];
__device__ __nv_bfloat16 g_wohi[DM * DM], g_wolo[DM * DM];

// ======================= helpers =======================
__device__ __forceinline__ uint32_t smem_u32(const void* p) {
    uint32_t a;
    asm("{ .reg .u64 t; cvta.to.shared.u64 t, %1; cvt.u32.u64 %0, t; }" : "=r"(a) : "l"(p));
    return a;
}
#define CP_ASYNC16(dst, src) \
    asm volatile("cp.async.cg.shared.global [%0], [%1], 16;" :: "r"(dst), "l"(src) : "memory")
#define CP_COMMIT() asm volatile("cp.async.commit_group;" ::: "memory")
#define CP_WAIT(n)  asm volatile("cp.async.wait_group %0;" :: "n"(n) : "memory")
#define SWZ(off) ((off) ^ (((off) >> 3) & 0x70))

__device__ __forceinline__ void ldm4(uint32_t addr, uint32_t* r) {
    asm volatile("ldmatrix.sync.aligned.m8n8.x4.shared.b16 {%0,%1,%2,%3}, [%4];"
                 : "=r"(r[0]), "=r"(r[1]), "=r"(r[2]), "=r"(r[3]) : "r"(addr));
}
__device__ __forceinline__ void mma16816(float* c, const uint32_t* a, const uint32_t* b) {
    asm volatile(
        "mma.sync.aligned.m16n8k16.row.col.f32.bf16.bf16.f32 "
        "{%0,%1,%2,%3}, {%4,%5,%6,%7}, {%8,%9}, {%0,%1,%2,%3};"
        : "+f"(c[0]), "+f"(c[1]), "+f"(c[2]), "+f"(c[3])
        : "r"(a[0]), "r"(a[1]), "r"(a[2]), "r"(a[3]), "r"(b[0]), "r"(b[1]));
}

// ---------------- fp32 -> bf16 hi/lo split (elementwise) ----------------
__global__ __launch_bounds__(256)
void split_kernel(const float* __restrict__ src, __nv_bfloat16* __restrict__ hi,
                  __nv_bfloat16* __restrict__ lo, int n4)
{
    int i = blockIdx.x * blockDim.x + threadIdx.x;
    if (i >= n4) return;
    float4 v = ((const float4*)src)[i];
    __nv_bfloat16 hx = __float2bfloat16(v.x), hy = __float2bfloat16(v.y),
                  hz = __float2bfloat16(v.z), hw = __float2bfloat16(v.w);
    ((ushort4*)hi)[i] = make_ushort4(__bfloat16_as_ushort(hx), __bfloat16_as_ushort(hy),
                                     __bfloat16_as_ushort(hz), __bfloat16_as_ushort(hw));
    __nv_bfloat16 lx = __float2bfloat16(v.x - __bfloat162float(hx));
    __nv_bfloat16 ly = __float2bfloat16(v.y - __bfloat162float(hy));
    __nv_bfloat16 lz = __float2bfloat16(v.z - __bfloat162float(hz));
    __nv_bfloat16 lw = __float2bfloat16(v.w - __bfloat162float(hw));
    ((ushort4*)lo)[i] = make_ushort4(__bfloat16_as_ushort(lx), __bfloat16_as_ushort(ly),
                                     __bfloat16_as_ushort(lz), __bfloat16_as_ushort(lw));
}

// =================== tensor-core GEMM: C[2048,1024] = A[2048,1024] * B[1024,1024]^T ===================
// A,B given as bf16 hi/lo pairs; fp32 accum via 3-term split (hh + hl + lh).
// CTA tile 128x128, K-chunk 64, double-buffered cp.async, swizzled smem, ldmatrix + mma.sync.
#define STAGE_BYTES 65536           // 4 matrices * 128 rows * 128B
#define GEMM_SMEM (2 * STAGE_BYTES) // 131072

__device__ __forceinline__ void stage_load(
    uint32_t sb, int stage, int tid, int m0, int n0, int k0,
    const __nv_bfloat16* __restrict__ Ahi, const __nv_bfloat16* __restrict__ Alo,
    const __nv_bfloat16* __restrict__ Bhi, const __nv_bfloat16* __restrict__ Blo)
{
#pragma unroll
    for (int i = 0; i < 16; i++) {
        const int mi = i >> 2;                        // 0:Ahi 1:Alo 2:Bhi 3:Blo
        const int cid = ((i & 3) << 8) + tid;         // 0..1023
        const int row = cid >> 3;                     // 0..127
        const int c16 = cid & 7;                      // 16B unit in row
        const __nv_bfloat16* g = (mi == 0) ? Ahi : (mi == 1) ? Alo : (mi == 2) ? Bhi : Blo;
        const int grow = ((mi < 2) ? m0 : n0) + row;
        const void* src = g + (size_t)grow * DM + k0 + c16 * 8;
        uint32_t off = (uint32_t)(row * 128 + c16 * 16);
        uint32_t dst = sb + stage * STAGE_BYTES + mi * 16384 + SWZ(off);
        CP_ASYNC16(dst, src);
    }
    CP_COMMIT();
}

__global__ __launch_bounds__(256, 1)
void gemm_bs(const __nv_bfloat16* __restrict__ Ahi, const __nv_bfloat16* __restrict__ Alo,
             const __nv_bfloat16* __restrict__ Bhi, const __nv_bfloat16* __restrict__ Blo,
             float* __restrict__ C)
{
    extern __shared__ char smem[];
    const uint32_t sb = smem_u32(smem);
    const int tid = threadIdx.x;
    const int wid = tid >> 5;
    const int lane = tid & 31;
    const int m0 = blockIdx.y * 128;
    const int n0 = blockIdx.x * 128;
    const int wm = (wid & 3) * 32;       // warp m offset in tile
    const int wn = (wid >> 2) * 64;      // warp n offset in tile

    float acc[2][8][4];
#pragma unroll
    for (int mt = 0; mt < 2; mt++)
#pragma unroll
        for (int nt = 0; nt < 8; nt++)
#pragma unroll
            for (int j = 0; j < 4; j++) acc[mt][nt][j] = 0.f;

    stage_load(sb, 0, tid, m0, n0, 0, Ahi, Alo, Bhi, Blo);

    for (int ch = 0; ch < 16; ch++) {
        if (ch < 15) {
            stage_load(sb, (ch + 1) & 1, tid, m0, n0, (ch + 1) * 64, Ahi, Alo, Bhi, Blo);
            CP_WAIT(1);
        } else {
            CP_WAIT(0);
        }
        __syncthreads();

        const uint32_t sA_hi = sb + (ch & 1) * STAGE_BYTES;
        const uint32_t sA_lo = sA_hi + 16384;
        const uint32_t sB_hi = sA_hi + 32768;
        const uint32_t sB_lo = sA_hi + 49152;

#pragma unroll
        for (int kk = 0; kk < 4; kk++) {
            const int kb = kk * 32 + ((lane >> 4) & 1) * 16;   // byte col for this lane

            uint32_t ahi[2][4], alo[2][4];
#pragma unroll
            for (int mt = 0; mt < 2; mt++) {
                uint32_t off = (uint32_t)((wm + mt * 16 + (lane & 15)) * 128 + kb);
                uint32_t so = SWZ(off);
                ldm4(sA_hi + so, ahi[mt]);
                ldm4(sA_lo + so, alo[mt]);
            }

            uint32_t bhi[8][2], blo[8][2];
#pragma unroll
            for (int p = 0; p < 4; p++) {
                uint32_t off = (uint32_t)((wn + p * 16 + (lane & 15)) * 128 + kb);
                uint32_t so = SWZ(off);
                uint32_t t[4];
                ldm4(sB_hi + so, t);
                bhi[2 * p][0] = t[0]; bhi[2 * p + 1][0] = t[1];
                bhi[2 * p][1] = t[2]; bhi[2 * p + 1][1] = t[3];
                ldm4(sB_lo + so, t);
                blo[2 * p][0] = t[0]; blo[2 * p + 1][0] = t[1];
                blo[2 * p][1] = t[2]; blo[2 * p + 1][1] = t[3];
            }

#pragma unroll
            for (int mt = 0; mt < 2; mt++)
#pragma unroll
                for (int nt = 0; nt < 8; nt++) {
                    mma16816(acc[mt][nt], ahi[mt], bhi[nt]);
                    mma16816(acc[mt][nt], ahi[mt], blo[nt]);
                    mma16816(acc[mt][nt], alo[mt], bhi[nt]);
                }
        }
        __syncthreads();
    }

    // epilogue
#pragma unroll
    for (int mt = 0; mt < 2; mt++) {
        const int r0 = m0 + wm + mt * 16 + (lane >> 2);
#pragma unroll
        for (int nt = 0; nt < 8; nt++) {
            const int c0 = n0 + wn + nt * 8 + 2 * (lane & 3);
            *(float2*)(C + (size_t)r0 * DM + c0)       = make_float2(acc[mt][nt][0], acc[mt][nt][1]);
            *(float2*)(C + (size_t)(r0 + 8) * DM + c0) = make_float2(acc[mt][nt][2], acc[mt][nt][3]);
        }
    }
}

// ---------------- beta = 2*sigmoid(x @ Wb^T), one warp per head ----------------
__global__ __launch_bounds__(512)
void beta_kernel(const float* __restrict__ x, const float* __restrict__ Wb)
{
    int token = blockIdx.x;
    int w = threadIdx.x >> 5;
    int lane = threadIdx.x & 31;
    const float* xr = x + (size_t)token * DM;
    const float* wr = Wb + (size_t)w * DM;
    float s = 0.f;
    for (int j = lane; j < DM; j += 32) s += xr[j] * wr[j];
#pragma unroll
    for (int o = 16; o; o >>= 1) s += __shfl_xor_sync(0xffffffffu, s, o);
    if (lane == 0) g_beta[token * NH + w] = 2.f / (1.f + __expf(-s));
}

__device__ __forceinline__ float silu(float v) { return v / (1.f + __expf(-v)); }

// ------- silu + per-head L2 normalize for q,k; silu for v (in place) -------
__global__ __launch_bounds__(256)
void act_kernel()
{
    int token = blockIdx.x;
    int tid = threadIdx.x;
    size_t off = (size_t)token * DM + tid * 4;

    float4 q = *(float4*)(g_qraw + off);
    q.x = silu(q.x); q.y = silu(q.y); q.z = silu(q.z); q.w = silu(q.w);
    float ss = q.x * q.x + q.y * q.y + q.z * q.z + q.w * q.w;
#pragma unroll
    for (int o = 8; o; o >>= 1) ss += __shfl_xor_sync(0xffffffffu, ss, o);
    float inv = 1.f / (sqrtf(ss) + 1e-6f);
    q.x *= inv; q.y *= inv; q.z *= inv; q.w *= inv;
    *(float4*)(g_qraw + off) = q;

    float4 k = *(float4*)(g_kraw + off);
    k.x = silu(k.x); k.y = silu(k.y); k.z = silu(k.z); k.w = silu(k.w);
    float sk = k.x * k.x + k.y * k.y + k.z * k.z + k.w * k.w;
#pragma unroll
    for (int o = 8; o; o >>= 1) sk += __shfl_xor_sync(0xffffffffu, sk, o);
    float invk = 1.f / (sqrtf(sk) + 1e-6f);
    k.x *= invk; k.y *= invk; k.z *= invk; k.w *= invk;
    *(float4*)(g_kraw + off) = k;

    float4 v = *(float4*)(g_vraw + off);
    v.x = silu(v.x); v.y = silu(v.y); v.z = silu(v.z); v.w = silu(v.w);
    *(float4*)(g_vraw + off) = v;
}

// ---------------- sequential delta-rule scan (dual-layout state) ----------------
__global__ __launch_bounds__(256, 1)
void scan_kernel()
{
    const int pair = blockIdx.x;
    const int b = pair >> 4, h = pair & 15;
    const int tid = threadIdx.x;
    const int lane64 = tid & 63;
    const int qr = tid >> 6;
    const int base = qr * 16;

    __shared__ float q_sh[64], k_sh[64], v_sh[64], bd_sh[64];
    __shared__ float partR[4][64], partO[4][64];
    __shared__ float beta_sh;

    float mcol[16], mrow[16];
#pragma unroll
    for (int i = 0; i < 16; i++) { mcol[i] = 0.f; mrow[i] = 0.f; }

    const size_t hb = (size_t)b * 1024 * DM + h * HD;
    const float* qp = g_qraw + hb;
    const float* kp = g_kraw + hb;
    const float* vp = g_vraw + hb;
    const float* bp = g_beta + (size_t)b * 1024 * NH + h;
    float* op = g_att + hb;

    for (int t = 0; t < 1024; t++) {
        if (tid < 64)        q_sh[tid]        = qp[(size_t)t * DM + tid];
        else if (tid < 128)  k_sh[tid - 64]   = kp[(size_t)t * DM + tid - 64];
        else if (tid < 192)  v_sh[tid - 128]  = vp[(size_t)t * DM + tid - 128];
        else if (tid == 192) beta_sh          = bp[(size_t)t * NH];
        __syncthreads();

        float pr = 0.f, po = 0.f;
#pragma unroll
        for (int i = 0; i < 16; i++) {
            pr += mrow[i] * k_sh[base + i];
            po += q_sh[base + i] * mcol[i];
        }
        partR[qr][lane64] = pr;
        partO[qr][lane64] = po;
        __syncthreads();

        if (tid < 64) {
            float rs = partR[0][tid] + partR[1][tid] + partR[2][tid] + partR[3][tid];
            bd_sh[tid] = beta_sh * (v_sh[tid] - rs);
        } else if (tid < 128) {
            int c = tid - 64;
            float os = partO[0][c] + partO[1][c] + partO[2][c] + partO[3][c];
            op[(size_t)t * DM + c] = os;
        }
        __syncthreads();

        const float bdc = bd_sh[lane64];
        const float kr  = k_sh[lane64];
#pragma unroll
        for (int i = 0; i < 16; i++) {
            mcol[i] += k_sh[base + i] * bdc;
            mrow[i] += kr * bd_sh[base + i];
        }
        __syncthreads();
    }
}

// ---------------- RMSNorm (in place on g_att) ----------------
__global__ __launch_bounds__(256)
void rms_kernel(const float* __restrict__ w)
{
    int token = blockIdx.x;
    int tid = threadIdx.x;
    size_t off = (size_t)token * DM + tid * 4;
    float4 v = *(float4*)(g_att + off);
    float ss = v.x * v.x + v.y * v.y + v.z * v.z + v.w * v.w;
#pragma unroll
    for (int o = 16; o; o >>= 1) ss += __shfl_xor_sync(0xffffffffu, ss, o);
    __shared__ float sh[8];
    __shared__ float sscale;
    if ((tid & 31) == 0) sh[tid >> 5] = ss;
    __syncthreads();
    if (tid == 0) {
        float t = 0.f;
#pragma unroll
        for (int i = 0; i < 8; i++) t += sh[i];
        sscale = 1.f / sqrtf(t / (float)DM + 1e-6f);
    }
    __syncthreads();
    float s = sscale;
    v.x *= s * w[tid * 4 + 0];
    v.y *= s * w[tid * 4 + 1];
    v.z *= s * w[tid * 4 + 2];
    v.w *= s * w[tid * 4 + 3];
    *(float4*)(g_att + off) = v;
}

// ---------------- launch ----------------
extern "C" void kernel_launch(void* const* d_in, const int* in_sizes, int n_in,
                              void* d_out, int out_size)
{
    const float* x    = (const float*)d_in[0];
    const float* Wq   = (const float*)d_in[1];
    const float* Wk   = (const float*)d_in[2];
    const float* Wv   = (const float*)d_in[3];
    const float* Wb   = (const float*)d_in[4];
    const float* Wo   = (const float*)d_in[5];
    const float* rmsw = (const float*)d_in[6];
    float* out = (float*)d_out;

    // symbol addresses (host-side queries, capture-safe)
    float *p_qraw, *p_kraw, *p_vraw, *p_att;
    __nv_bfloat16 *p_xhi, *p_xlo, *p_atthi, *p_attlo;
    __nv_bfloat16 *p_wqhi, *p_wqlo, *p_wkhi, *p_wklo, *p_wvhi, *p_wvlo, *p_wohi, *p_wolo;
    cudaGetSymbolAddress((void**)&p_qraw, g_qraw);
    cudaGetSymbolAddress((void**)&p_kraw, g_kraw);
    cudaGetSymbolAddress((void**)&p_vraw, g_vraw);
    cudaGetSymbolAddress((void**)&p_att,  g_att);
    cudaGetSymbolAddress((void**)&p_xhi,  g_xhi);
    cudaGetSymbolAddress((void**)&p_xlo,  g_xlo);
    cudaGetSymbolAddress((void**)&p_atthi, g_atthi);
    cudaGetSymbolAddress((void**)&p_attlo, g_attlo);
    cudaGetSymbolAddress((void**)&p_wqhi, g_wqhi);
    cudaGetSymbolAddress((void**)&p_wqlo, g_wqlo);
    cudaGetSymbolAddress((void**)&p_wkhi, g_wkhi);
    cudaGetSymbolAddress((void**)&p_wklo, g_wklo);
    cudaGetSymbolAddress((void**)&p_wvhi, g_wvhi);
    cudaGetSymbolAddress((void**)&p_wvlo, g_wvlo);
    cudaGetSymbolAddress((void**)&p_wohi, g_wohi);
    cudaGetSymbolAddress((void**)&p_wolo, g_wolo);

    cudaFuncSetAttribute(gemm_bs, cudaFuncAttributeMaxDynamicSharedMemorySize, GEMM_SMEM);

    const int n4x = TOKENS * DM / 4;   // 524288
    const int n4w = DM * DM / 4;       // 262144
    split_kernel<<<n4x / 256, 256>>>(x,  p_xhi,  p_xlo,  n4x);
    split_kernel<<<n4w / 256, 256>>>(Wq, p_wqhi, p_wqlo, n4w);
    split_kernel<<<n4w / 256, 256>>>(Wk, p_wkhi, p_wklo, n4w);
    split_kernel<<<n4w / 256, 256>>>(Wv, p_wvhi, p_wvlo, n4w);
    split_kernel<<<n4w / 256, 256>>>(Wo, p_wohi, p_wolo, n4w);

    dim3 gg(DM / 128, TOKENS / 128);   // (8, 16) = 128 CTAs
    gemm_bs<<<gg, 256, GEMM_SMEM>>>(p_xhi, p_xlo, p_wqhi, p_wqlo, p_qraw);
    gemm_bs<<<gg, 256, GEMM_SMEM>>>(p_xhi, p_xlo, p_wkhi, p_wklo, p_kraw);
    gemm_bs<<<gg, 256, GEMM_SMEM>>>(p_xhi, p_xlo, p_wvhi, p_wvlo, p_vraw);
    beta_kernel<<<TOKENS, 512>>>(x, Wb);
    act_kernel<<<TOKENS, 256>>>();
    scan_kernel<<<32, 256>>>();
    rms_kernel<<<TOKENS, 256>>>(rmsw);
    split_kernel<<<n4x / 256, 256>>>(p_att, p_atthi, p_attlo, n4x);
    gemm_bs<<<gg, 256, GEMM_SMEM>>>(p_atthi, p_attlo, p_wohi, p_wolo, out);
}

// round 5
// speedup vs baseline: 2.5195x; 1.7329x over previous
#include <cuda_runtime.h>
#include <cuda_bf16.h>
#include <math.h>
#include <stdint.h>

#define TOKENS 2048
#define DM 1024
#define NH 16
#define HD 64

// ---------------- scratch (device globals: no allocs allowed) ----------------
__device__ float g_qraw[TOKENS * DM];
__device__ float g_kraw[TOKENS * DM];
__device__ float g_vraw[TOKENS * DM];
__device__ float g_beta[TOKENS * NH];
__device__ float g_att [TOKENS * DM];

__device__ __nv_bfloat16 g_xhi[TOKENS * DM], g_xlo[TOKENS * DM];
__device__ __nv_bfloat16 g_atthi[TOKENS * DM], g_attlo[TOKENS * DM];
__device__ __nv_bfloat16 g_wqhi[DM * DM], g_wqlo[DM * DM];
__device__ __nv_bfloat16 g_wkhi[DM * DM], g_wklo[DM * DM];
__device__ __nv_bfloat16 g_wvhi[DM * DM], g_wvlo[DM * DM];
__device__ __nv_bfloat16 g_wohi[DM * DM], g_wolo[DM * DM];

// ======================= helpers =======================
__device__ __forceinline__ uint32_t smem_u32(const void* p) {
    uint32_t a;
    asm("{ .reg .u64 t; cvta.to.shared.u64 t, %1; cvt.u32.u64 %0, t; }" : "=r"(a) : "l"(p));
    return a;
}
#define CP_ASYNC16(dst, src) \
    asm volatile("cp.async.cg.shared.global [%0], [%1], 16;" :: "r"(dst), "l"(src) : "memory")
#define CP_ASYNC4(dst, src) \
    asm volatile("cp.async.ca.shared.global [%0], [%1], 4;" :: "r"(dst), "l"(src) : "memory")
#define CP_COMMIT() asm volatile("cp.async.commit_group;" ::: "memory")
#define CP_WAIT(n)  asm volatile("cp.async.wait_group %0;" :: "n"(n) : "memory")
#define SWZ(off) ((off) ^ (((off) >> 3) & 0x70))

__device__ __forceinline__ void ldm4(uint32_t addr, uint32_t* r) {
    asm volatile("ldmatrix.sync.aligned.m8n8.x4.shared.b16 {%0,%1,%2,%3}, [%4];"
                 : "=r"(r[0]), "=r"(r[1]), "=r"(r[2]), "=r"(r[3]) : "r"(addr));
}
__device__ __forceinline__ void mma16816(float* c, const uint32_t* a, const uint32_t* b) {
    asm volatile(
        "mma.sync.aligned.m16n8k16.row.col.f32.bf16.bf16.f32 "
        "{%0,%1,%2,%3}, {%4,%5,%6,%7}, {%8,%9}, {%0,%1,%2,%3};"
        : "+f"(c[0]), "+f"(c[1]), "+f"(c[2]), "+f"(c[3])
        : "r"(a[0]), "r"(a[1]), "r"(a[2]), "r"(a[3]), "r"(b[0]), "r"(b[1]));
}

// ---------------- fp32 -> bf16 hi/lo split (elementwise) ----------------
__global__ __launch_bounds__(256)
void split_kernel(const float* __restrict__ src, __nv_bfloat16* __restrict__ hi,
                  __nv_bfloat16* __restrict__ lo, int n4)
{
    int i = blockIdx.x * blockDim.x + threadIdx.x;
    if (i >= n4) return;
    float4 v = ((const float4*)src)[i];
    __nv_bfloat16 hx = __float2bfloat16(v.x), hy = __float2bfloat16(v.y),
                  hz = __float2bfloat16(v.z), hw = __float2bfloat16(v.w);
    ((ushort4*)hi)[i] = make_ushort4(__bfloat16_as_ushort(hx), __bfloat16_as_ushort(hy),
                                     __bfloat16_as_ushort(hz), __bfloat16_as_ushort(hw));
    __nv_bfloat16 lx = __float2bfloat16(v.x - __bfloat162float(hx));
    __nv_bfloat16 ly = __float2bfloat16(v.y - __bfloat162float(hy));
    __nv_bfloat16 lz = __float2bfloat16(v.z - __bfloat162float(hz));
    __nv_bfloat16 lw = __float2bfloat16(v.w - __bfloat162float(hw));
    ((ushort4*)lo)[i] = make_ushort4(__bfloat16_as_ushort(lx), __bfloat16_as_ushort(ly),
                                     __bfloat16_as_ushort(lz), __bfloat16_as_ushort(lw));
}

// =================== tensor-core GEMM: C[2048,1024] = A[2048,1024] * B[1024,1024]^T ===================
#define STAGE_BYTES 65536
#define GEMM_SMEM (2 * STAGE_BYTES)

__device__ __forceinline__ void stage_load(
    uint32_t sb, int stage, int tid, int m0, int n0, int k0,
    const __nv_bfloat16* __restrict__ Ahi, const __nv_bfloat16* __restrict__ Alo,
    const __nv_bfloat16* __restrict__ Bhi, const __nv_bfloat16* __restrict__ Blo)
{
#pragma unroll
    for (int i = 0; i < 16; i++) {
        const int mi = i >> 2;
        const int cid = ((i & 3) << 8) + tid;
        const int row = cid >> 3;
        const int c16 = cid & 7;
        const __nv_bfloat16* g = (mi == 0) ? Ahi : (mi == 1) ? Alo : (mi == 2) ? Bhi : Blo;
        const int grow = ((mi < 2) ? m0 : n0) + row;
        const void* src = g + (size_t)grow * DM + k0 + c16 * 8;
        uint32_t off = (uint32_t)(row * 128 + c16 * 16);
        uint32_t dst = sb + stage * STAGE_BYTES + mi * 16384 + SWZ(off);
        CP_ASYNC16(dst, src);
    }
    CP_COMMIT();
}

__global__ __launch_bounds__(256, 1)
void gemm_bs(const __nv_bfloat16* __restrict__ Ahi, const __nv_bfloat16* __restrict__ Alo,
             const __nv_bfloat16* __restrict__ Bhi, const __nv_bfloat16* __restrict__ Blo,
             float* __restrict__ C)
{
    extern __shared__ char smem[];
    const uint32_t sb = smem_u32(smem);
    const int tid = threadIdx.x;
    const int wid = tid >> 5;
    const int lane = tid & 31;
    const int m0 = blockIdx.y * 128;
    const int n0 = blockIdx.x * 128;
    const int wm = (wid & 3) * 32;
    const int wn = (wid >> 2) * 64;

    float acc[2][8][4];
#pragma unroll
    for (int mt = 0; mt < 2; mt++)
#pragma unroll
        for (int nt = 0; nt < 8; nt++)
#pragma unroll
            for (int j = 0; j < 4; j++) acc[mt][nt][j] = 0.f;

    stage_load(sb, 0, tid, m0, n0, 0, Ahi, Alo, Bhi, Blo);

    for (int ch = 0; ch < 16; ch++) {
        if (ch < 15) {
            stage_load(sb, (ch + 1) & 1, tid, m0, n0, (ch + 1) * 64, Ahi, Alo, Bhi, Blo);
            CP_WAIT(1);
        } else {
            CP_WAIT(0);
        }
        __syncthreads();

        const uint32_t sA_hi = sb + (ch & 1) * STAGE_BYTES;
        const uint32_t sA_lo = sA_hi + 16384;
        const uint32_t sB_hi = sA_hi + 32768;
        const uint32_t sB_lo = sA_hi + 49152;

#pragma unroll
        for (int kk = 0; kk < 4; kk++) {
            const int kb = kk * 32 + ((lane >> 4) & 1) * 16;

            uint32_t ahi[2][4], alo[2][4];
#pragma unroll
            for (int mt = 0; mt < 2; mt++) {
                uint32_t off = (uint32_t)((wm + mt * 16 + (lane & 15)) * 128 + kb);
                uint32_t so = SWZ(off);
                ldm4(sA_hi + so, ahi[mt]);
                ldm4(sA_lo + so, alo[mt]);
            }

            uint32_t bhi[8][2], blo[8][2];
#pragma unroll
            for (int p = 0; p < 4; p++) {
                uint32_t off = (uint32_t)((wn + p * 16 + (lane & 15)) * 128 + kb);
                uint32_t so = SWZ(off);
                uint32_t t[4];
                ldm4(sB_hi + so, t);
                bhi[2 * p][0] = t[0]; bhi[2 * p + 1][0] = t[1];
                bhi[2 * p][1] = t[2]; bhi[2 * p + 1][1] = t[3];
                ldm4(sB_lo + so, t);
                blo[2 * p][0] = t[0]; blo[2 * p + 1][0] = t[1];
                blo[2 * p][1] = t[2]; blo[2 * p + 1][1] = t[3];
            }

#pragma unroll
            for (int mt = 0; mt < 2; mt++)
#pragma unroll
                for (int nt = 0; nt < 8; nt++) {
                    mma16816(acc[mt][nt], ahi[mt], bhi[nt]);
                    mma16816(acc[mt][nt], ahi[mt], blo[nt]);
                    mma16816(acc[mt][nt], alo[mt], bhi[nt]);
                }
        }
        __syncthreads();
    }

#pragma unroll
    for (int mt = 0; mt < 2; mt++) {
        const int r0 = m0 + wm + mt * 16 + (lane >> 2);
#pragma unroll
        for (int nt = 0; nt < 8; nt++) {
            const int c0 = n0 + wn + nt * 8 + 2 * (lane & 3);
            *(float2*)(C + (size_t)r0 * DM + c0)       = make_float2(acc[mt][nt][0], acc[mt][nt][1]);
            *(float2*)(C + (size_t)(r0 + 8) * DM + c0) = make_float2(acc[mt][nt][2], acc[mt][nt][3]);
        }
    }
}

// ---------------- beta = 2*sigmoid(x @ Wb^T), one warp per head ----------------
__global__ __launch_bounds__(512)
void beta_kernel(const float* __restrict__ x, const float* __restrict__ Wb)
{
    int token = blockIdx.x;
    int w = threadIdx.x >> 5;
    int lane = threadIdx.x & 31;
    const float* xr = x + (size_t)token * DM;
    const float* wr = Wb + (size_t)w * DM;
    float s = 0.f;
    for (int j = lane; j < DM; j += 32) s += xr[j] * wr[j];
#pragma unroll
    for (int o = 16; o; o >>= 1) s += __shfl_xor_sync(0xffffffffu, s, o);
    if (lane == 0) g_beta[token * NH + w] = 2.f / (1.f + __expf(-s));
}

__device__ __forceinline__ float silu(float v) { return v / (1.f + __expf(-v)); }

// ------- silu + per-head L2 normalize for q,k; silu for v (in place) -------
__global__ __launch_bounds__(256)
void act_kernel()
{
    int token = blockIdx.x;
    int tid = threadIdx.x;
    size_t off = (size_t)token * DM + tid * 4;

    float4 q = *(float4*)(g_qraw + off);
    q.x = silu(q.x); q.y = silu(q.y); q.z = silu(q.z); q.w = silu(q.w);
    float ss = q.x * q.x + q.y * q.y + q.z * q.z + q.w * q.w;
#pragma unroll
    for (int o = 8; o; o >>= 1) ss += __shfl_xor_sync(0xffffffffu, ss, o);
    float inv = 1.f / (sqrtf(ss) + 1e-6f);
    q.x *= inv; q.y *= inv; q.z *= inv; q.w *= inv;
    *(float4*)(g_qraw + off) = q;

    float4 k = *(float4*)(g_kraw + off);
    k.x = silu(k.x); k.y = silu(k.y); k.z = silu(k.z); k.w = silu(k.w);
    float sk = k.x * k.x + k.y * k.y + k.z * k.z + k.w * k.w;
#pragma unroll
    for (int o = 8; o; o >>= 1) sk += __shfl_xor_sync(0xffffffffu, sk, o);
    float invk = 1.f / (sqrtf(sk) + 1e-6f);
    k.x *= invk; k.y *= invk; k.z *= invk; k.w *= invk;
    *(float4*)(g_kraw + off) = k;

    float4 v = *(float4*)(g_vraw + off);
    v.x = silu(v.x); v.y = silu(v.y); v.z = silu(v.z); v.w = silu(v.w);
    *(float4*)(g_vraw + off) = v;
}

// ---------------- sequential delta-rule scan: cp.async prefetch + 2 barriers/step ----------------
#define SBLK 8
#define NBLK (1024 / SBLK)

__global__ __launch_bounds__(256, 1)
void scan_kernel()
{
    const int pair = blockIdx.x;
    const int b = pair >> 4, h = pair & 15;
    const int tid = threadIdx.x;
    const int lane64 = tid & 63;
    const int qr = tid >> 6;
    const int base = qr * 16;

    __shared__ float ring[2][3][SBLK][64];   // [buf][q/k/v][step][dim]
    __shared__ float ring_b[2][SBLK];
    __shared__ float partR[2][4][64], partO[2][4][64];
    __shared__ float bd_sh[2][64];

    float mcol[16], mrow[16];
#pragma unroll
    for (int i = 0; i < 16; i++) { mcol[i] = 0.f; mrow[i] = 0.f; }

    const size_t hb = (size_t)b * 1024 * DM + h * HD;
    const float* qp = g_qraw + hb;
    const float* kp = g_kraw + hb;
    const float* vp = g_vraw + hb;
    const float* bp = g_beta + (size_t)b * 1024 * NH + h;
    float* op = g_att + hb;

    // prefetch one 8-step block into buffer `buf`
    auto prefetch = [&](int blk, int buf) {
        const int t0 = blk * SBLK;
#pragma unroll
        for (int i = 0; i < 2; i++) {
            int idx = tid + i * 256;
            if (idx < 384) {
                int arr = idx >> 7;          // 0=q 1=k 2=v
                int rem = idx & 127;
                int s = rem >> 4;
                int c = (rem & 15) * 4;
                const float* src = (arr == 0 ? qp : arr == 1 ? kp : vp)
                                   + (size_t)(t0 + s) * DM + c;
                CP_ASYNC16(smem_u32(&ring[buf][arr][s][c]), src);
            }
        }
        if (tid < SBLK)
            CP_ASYNC4(smem_u32(&ring_b[buf][tid]), bp + (size_t)(t0 + tid) * NH);
        CP_COMMIT();
    };

    prefetch(0, 0);
    prefetch(1, 1);

    for (int blk = 0; blk < NBLK; blk++) {
        const int buf = blk & 1;
        CP_WAIT(1);
        __syncthreads();

#pragma unroll
        for (int s = 0; s < SBLK; s++) {
            const int t = blk * SBLK + s;
            const int p = t & 1;
            const float* q_sh = ring[buf][0][s];
            const float* k_sh = ring[buf][1][s];
            const float* v_sh = ring[buf][2][s];

            // cache k slice in registers (reused in update)
            float kreg[16];
#pragma unroll
            for (int i = 0; i < 16; i++) kreg[i] = k_sh[base + i];

            float pr0 = 0.f, pr1 = 0.f, po0 = 0.f, po1 = 0.f;
#pragma unroll
            for (int i = 0; i < 16; i += 2) {
                pr0 += mrow[i]     * kreg[i];
                pr1 += mrow[i + 1] * kreg[i + 1];
                po0 += q_sh[base + i]     * mcol[i];
                po1 += q_sh[base + i + 1] * mcol[i + 1];
            }
            partR[p][qr][lane64] = pr0 + pr1;
            partO[p][qr][lane64] = po0 + po1;
            __syncthreads();

            if (tid < 64) {
                float rs = partR[p][0][tid] + partR[p][1][tid]
                         + partR[p][2][tid] + partR[p][3][tid];
                bd_sh[p][tid] = ring_b[buf][s] * (v_sh[tid] - rs);
            } else if (tid < 128) {
                int c = tid - 64;
                float os = partO[p][0][c] + partO[p][1][c]
                         + partO[p][2][c] + partO[p][3][c];
                op[(size_t)t * DM + c] = os;
            }
            __syncthreads();

            const float bdc = bd_sh[p][lane64];
            const float kr  = k_sh[lane64];
#pragma unroll
            for (int i = 0; i < 16; i++) {
                mcol[i] += kreg[i] * bdc;
                mrow[i] += kr * bd_sh[p][base + i];
            }
            // no barrier: next step writes opposite-parity buffers
        }

        if (blk + 2 < NBLK) {
            __syncthreads();              // all reads of ring[buf] done
            prefetch(blk + 2, buf);
        } else {
            CP_COMMIT();                  // keep wait_group accounting aligned
        }
    }
}

// ---------------- RMSNorm (in place on g_att) ----------------
__global__ __launch_bounds__(256)
void rms_kernel(const float* __restrict__ w)
{
    int token = blockIdx.x;
    int tid = threadIdx.x;
    size_t off = (size_t)token * DM + tid * 4;
    float4 v = *(float4*)(g_att + off);
    float ss = v.x * v.x + v.y * v.y + v.z * v.z + v.w * v.w;
#pragma unroll
    for (int o = 16; o; o >>= 1) ss += __shfl_xor_sync(0xffffffffu, ss, o);
    __shared__ float sh[8];
    __shared__ float sscale;
    if ((tid & 31) == 0) sh[tid >> 5] = ss;
    __syncthreads();
    if (tid == 0) {
        float t = 0.f;
#pragma unroll
        for (int i = 0; i < 8; i++) t += sh[i];
        sscale = 1.f / sqrtf(t / (float)DM + 1e-6f);
    }
    __syncthreads();
    float s = sscale;
    v.x *= s * w[tid * 4 + 0];
    v.y *= s * w[tid * 4 + 1];
    v.z *= s * w[tid * 4 + 2];
    v.w *= s * w[tid * 4 + 3];
    *(float4*)(g_att + off) = v;
}

// ---------------- launch ----------------
extern "C" void kernel_launch(void* const* d_in, const int* in_sizes, int n_in,
                              void* d_out, int out_size)
{
    const float* x    = (const float*)d_in[0];
    const float* Wq   = (const float*)d_in[1];
    const float* Wk   = (const float*)d_in[2];
    const float* Wv   = (const float*)d_in[3];
    const float* Wb   = (const float*)d_in[4];
    const float* Wo   = (const float*)d_in[5];
    const float* rmsw = (const float*)d_in[6];
    float* out = (float*)d_out;

    float *p_qraw, *p_kraw, *p_vraw, *p_att;
    __nv_bfloat16 *p_xhi, *p_xlo, *p_atthi, *p_attlo;
    __nv_bfloat16 *p_wqhi, *p_wqlo, *p_wkhi, *p_wklo, *p_wvhi, *p_wvlo, *p_wohi, *p_wolo;
    cudaGetSymbolAddress((void**)&p_qraw, g_qraw);
    cudaGetSymbolAddress((void**)&p_kraw, g_kraw);
    cudaGetSymbolAddress((void**)&p_vraw, g_vraw);
    cudaGetSymbolAddress((void**)&p_att,  g_att);
    cudaGetSymbolAddress((void**)&p_xhi,  g_xhi);
    cudaGetSymbolAddress((void**)&p_xlo,  g_xlo);
    cudaGetSymbolAddress((void**)&p_atthi, g_atthi);
    cudaGetSymbolAddress((void**)&p_attlo, g_attlo);
    cudaGetSymbolAddress((void**)&p_wqhi, g_wqhi);
    cudaGetSymbolAddress((void**)&p_wqlo, g_wqlo);
    cudaGetSymbolAddress((void**)&p_wkhi, g_wkhi);
    cudaGetSymbolAddress((void**)&p_wklo, g_wklo);
    cudaGetSymbolAddress((void**)&p_wvhi, g_wvhi);
    cudaGetSymbolAddress((void**)&p_wvlo, g_wvlo);
    cudaGetSymbolAddress((void**)&p_wohi, g_wohi);
    cudaGetSymbolAddress((void**)&p_wolo, g_wolo);

    cudaFuncSetAttribute(gemm_bs, cudaFuncAttributeMaxDynamicSharedMemorySize, GEMM_SMEM);

    const int n4x = TOKENS * DM / 4;
    const int n4w = DM * DM / 4;
    split_kernel<<<n4x / 256, 256>>>(x,  p_xhi,  p_xlo,  n4x);
    split_kernel<<<n4w / 256, 256>>>(Wq, p_wqhi, p_wqlo, n4w);
    split_kernel<<<n4w / 256, 256>>>(Wk, p_wkhi, p_wklo, n4w);
    split_kernel<<<n4w / 256, 256>>>(Wv, p_wvhi, p_wvlo, n4w);
    split_kernel<<<n4w / 256, 256>>>(Wo, p_wohi, p_wolo, n4w);

    dim3 gg(DM / 128, TOKENS / 128);
    gemm_bs<<<gg, 256, GEMM_SMEM>>>(p_xhi, p_xlo, p_wqhi, p_wqlo, p_qraw);
    gemm_bs<<<gg, 256, GEMM_SMEM>>>(p_xhi, p_xlo, p_wkhi, p_wklo, p_kraw);
    gemm_bs<<<gg, 256, GEMM_SMEM>>>(p_xhi, p_xlo, p_wvhi, p_wvlo, p_vraw);
    beta_kernel<<<TOKENS, 512>>>(x, Wb);
    act_kernel<<<TOKENS, 256>>>();
    scan_kernel<<<32, 256>>>();
    rms_kernel<<<TOKENS, 256>>>(rmsw);
    split_kernel<<<n4x / 256, 256>>>(p_att, p_atthi, p_attlo, n4x);
    gemm_bs<<<gg, 256, GEMM_SMEM>>>(p_atthi, p_attlo, p_wohi, p_wolo, out);
}